// round 1
// baseline (speedup 1.0000x reference)
#include <cuda_runtime.h>
#include <cuda_bf16.h>
#include <cstdint>

// Problem constants
#define TT   512
#define BB   64
#define HID  1024
#define LAY  4
#define NWAVE (TT + LAY - 1)   // 515

// Scratch (static __device__ — no allocations allowed)
// Hidden-state ring: 2 wave slots x [L][B][H] fp32 = 2 MB (L2 resident)
__device__ float g_ring[2][LAY][BB][HID];
// Packed split-bf16 weights, fragment-major:
// [matrix m=l*2+s][kc 0..63][row n 0..3071][tig 0..3] -> uint4 {hi(k0,k1), hi(k8,k9), lo(k0,k1), lo(k8,k9)}
// 8 * 64 * 3072 * 4 uint4 = 100.7 MB
__device__ uint4 g_wpack[8ull * 64 * 3072 * 4];

// ---------- helpers ----------
__device__ __forceinline__ void split_pair(float x, float y, uint32_t& hi, uint32_t& lo) {
    __nv_bfloat16 hx = __float2bfloat16(x);
    __nv_bfloat16 hy = __float2bfloat16(y);
    float rx = x - __bfloat162float(hx);
    float ry = y - __bfloat162float(hy);
    __nv_bfloat162 H2; H2.x = hx; H2.y = hy;
    __nv_bfloat162 L2 = __floats2bfloat162_rn(rx, ry);
    hi = *reinterpret_cast<uint32_t*>(&H2);
    lo = *reinterpret_cast<uint32_t*>(&L2);
}

__device__ __forceinline__ void mma_bf16(float* c, const uint32_t* a, uint32_t b0, uint32_t b1) {
    asm volatile(
        "mma.sync.aligned.m16n8k16.row.col.f32.bf16.bf16.f32 "
        "{%0,%1,%2,%3},{%4,%5,%6,%7},{%8,%9},{%0,%1,%2,%3};"
        : "+f"(c[0]), "+f"(c[1]), "+f"(c[2]), "+f"(c[3])
        : "r"(a[0]), "r"(a[1]), "r"(a[2]), "r"(a[3]), "r"(b0), "r"(b1));
}

// ---------- weight packing ----------
// One thread per output uint4: idx -> (m, kc, n, tig)
__global__ void pack_weights_kernel(const float* __restrict__ w_ih,
                                    const float* __restrict__ w_hh) {
    int64_t idx = (int64_t)blockIdx.x * blockDim.x + threadIdx.x;
    const int64_t total = 8ll * 64 * 3072 * 4;
    if (idx >= total) return;
    int tig = (int)(idx & 3);
    int64_t t2 = idx >> 2;
    int n = (int)(t2 % 3072);
    int64_t t3 = t2 / 3072;
    int kc = (int)(t3 & 63);
    int m  = (int)(t3 >> 6);
    int l = m >> 1, s = m & 1;
    const float* src = (s ? w_hh : w_ih) + ((int64_t)l * 3072 + n) * 1024 + kc * 16 + 2 * tig;
    float f0 = src[0], f1 = src[1], f2 = src[8], f3 = src[9];
    uint4 q;
    split_pair(f0, f1, q.x, q.z);
    split_pair(f2, f3, q.y, q.w);
    g_wpack[idx] = q;
}

// ---------- h0 init ----------
__global__ void init_h0_kernel(const float* __restrict__ h0) {
    int idx = blockIdx.x * blockDim.x + threadIdx.x;   // < L*B*H = 262144
    int l = idx >> 16;
    int rest = idx & 0xFFFF;
    int slot = (l + 1) & 1;                            // read-slot of wave l
    (&g_ring[slot][l][0][0])[rest] = h0[idx];
}

// ---------- wave kernel ----------
// grid = 128 (l = bx>>5, cb = bx&31), block = 256 threads (8 warps)
// warp = mstrip (0..3) x jhalf (0..1); each warp: rows [16*mstrip,+16), jt in {2*jhalf, 2*jhalf+1}
__global__ void __launch_bounds__(256, 1)
wave_kernel(const float* __restrict__ x,
            const float* __restrict__ b_ih,
            const float* __restrict__ b_hh,
            int w) {
    int l  = blockIdx.x >> 5;
    int cb = blockIdx.x & 31;
    int t  = w - l;
    if (t < 0 || t >= TT) return;

    const int rs = (w + 1) & 1;   // read slot (wave w-1 products + h0)
    const int ws = w & 1;         // write slot

    const float* inp   = (l == 0) ? (x + (int64_t)t * BB * HID) : &g_ring[rs][l - 1][0][0];
    const float* hprev = &g_ring[rs][l][0][0];
    float*       hout  = &g_ring[ws][l][0][0];

    const int lane = threadIdx.x & 31;
    const int warp = threadIdx.x >> 5;
    const int mstrip = warp & 3;
    const int jhalf  = warp >> 2;
    const int gid = lane >> 2;    // 0..7
    const int tig = lane & 3;     // 0..3
    const int c0 = cb * 32;

    // acc[group][jt_local][reg]; groups: 0=r(gi+gh), 1=z(gi+gh), 2=gi_n, 3=gh_n
    float acc[4][2][4];
#pragma unroll
    for (int g = 0; g < 4; ++g)
#pragma unroll
        for (int j = 0; j < 2; ++j)
#pragma unroll
            for (int r = 0; r < 4; ++r) acc[g][j][r] = 0.f;

    const int r0 = mstrip * 16 + gid;

#pragma unroll
    for (int phase = 0; phase < 2; ++phase) {
        const float* act = phase ? hprev : inp;
        const uint4* wp = &g_wpack[(int64_t)(l * 2 + phase) * 64 * 3072 * 4];
        const int g_third = phase ? 3 : 2;   // phase0 accumulates gi_n, phase1 gh_n

#pragma unroll 2
        for (int kc = 0; kc < 64; ++kc) {
            // ---- A fragments (activations, split on the fly) ----
            uint32_t Ah[4], Al[4];
            const float* ar0 = act + (int64_t)r0 * HID + kc * 16 + 2 * tig;
            const float* ar1 = ar0 + 8 * HID;
            float2 p;
            p = *(const float2*)(ar0);     split_pair(p.x, p.y, Ah[0], Al[0]);
            p = *(const float2*)(ar1);     split_pair(p.x, p.y, Ah[1], Al[1]);
            p = *(const float2*)(ar0 + 8); split_pair(p.x, p.y, Ah[2], Al[2]);
            p = *(const float2*)(ar1 + 8); split_pair(p.x, p.y, Ah[3], Al[3]);

            const uint4* wkc = wp + (int64_t)kc * 3072 * 4;

            // ---- B fragments + 3-term split MMAs ----
#pragma unroll
            for (int gg = 0; gg < 3; ++gg) {
                const int g = (gg < 2) ? gg : g_third;
                const int goff = gg * HID;  // weight row block: r@0, z@H, n@2H
#pragma unroll
                for (int jtl = 0; jtl < 2; ++jtl) {
                    const int jt = jhalf * 2 + jtl;
                    const int n = goff + c0 + jt * 8 + gid;
                    uint4 q = wkc[n * 4 + tig];
                    float* C = acc[g][jtl];
                    mma_bf16(C, Ah, q.x, q.y);   // Ah * Wh
                    mma_bf16(C, Ah, q.z, q.w);   // Ah * Wl
                    mma_bf16(C, Al, q.x, q.y);   // Al * Wh
                }
            }
        }
    }

    // ---- gates (thread-local: all 4 gate pre-acts for (b,c) live in same regs) ----
    const float* bi = b_ih + l * 3 * HID;
    const float* bh = b_hh + l * 3 * HID;
#pragma unroll
    for (int jtl = 0; jtl < 2; ++jtl) {
        const int jbase = (jhalf * 2 + jtl) * 8 + tig * 2;
#pragma unroll
        for (int half = 0; half < 2; ++half) {
            const int b = mstrip * 16 + gid + half * 8;
#pragma unroll
            for (int par = 0; par < 2; ++par) {
                const int c = c0 + jbase + par;
                const int ri = half * 2 + par;
                float pr  = acc[0][jtl][ri] + bi[c]           + bh[c];
                float pz  = acc[1][jtl][ri] + bi[HID + c]     + bh[HID + c];
                float gin = acc[2][jtl][ri] + bi[2 * HID + c];
                float ghn = acc[3][jtl][ri] + bh[2 * HID + c];
                float rr = 1.f / (1.f + __expf(-pr));
                float zz = 1.f / (1.f + __expf(-pz));
                float nn = tanhf(gin + rr * ghn);
                float hp = hprev[(int64_t)b * HID + c];
                hout[(int64_t)b * HID + c] = (1.f - zz) * nn + zz * hp;
            }
        }
    }
}

// ---------- output copy ----------
__global__ void copy_out_kernel(float* __restrict__ out) {
    int idx = blockIdx.x * blockDim.x + threadIdx.x;   // < L*B*H
    int l = idx >> 16;
    int rest = idx & 0xFFFF;
    int slot = (TT - 1 + l) & 1;  // slot of the final write of layer l (wave T-1+l)
    out[idx] = (&g_ring[slot][l][0][0])[rest];
}

// ---------- launch ----------
extern "C" void kernel_launch(void* const* d_in, const int* in_sizes, int n_in,
                              void* d_out, int out_size) {
    const float* x    = (const float*)d_in[0];
    const float* h0   = (const float*)d_in[1];
    const float* w_ih = (const float*)d_in[2];
    const float* w_hh = (const float*)d_in[3];
    const float* b_ih = (const float*)d_in[4];
    const float* b_hh = (const float*)d_in[5];
    float* out = (float*)d_out;

    // 1) pack weights into split-bf16 fragment-major layout (8*64*3072*4 uint4)
    {
        int64_t total = 8ll * 64 * 3072 * 4;
        int thr = 256;
        int blks = (int)((total + thr - 1) / thr);
        pack_weights_kernel<<<blks, thr>>>(w_ih, w_hh);
    }
    // 2) place h0 into each layer's first read slot
    init_h0_kernel<<<(LAY * BB * HID) / 256, 256>>>(h0);

    // 3) wavefront: 515 dependent waves, stream-ordered
    for (int w = 0; w < NWAVE; ++w) {
        wave_kernel<<<128, 256>>>(x, b_ih, b_hh, w);
    }

    // 4) gather final hidden states
    copy_out_kernel<<<(LAY * BB * HID) / 256, 256>>>(out);
}

// round 2
// speedup vs baseline: 1.4565x; 1.4565x over previous
#include <cuda_runtime.h>
#include <cuda_bf16.h>
#include <cstdint>

// Problem constants
#define TT   512
#define BB   64
#define HID  1024
#define LAY  4
#define NWAVE (TT + LAY - 1)   // 515

// Scratch (static __device__ — no allocations allowed)
// Hidden-state ring: 2 wave slots x [L][B][H] fp32 = 2 MB (L2 resident)
__device__ float g_ring[2][LAY][BB][HID];
// Packed split-bf16 weights, fragment-major:
// [matrix m=l*2+s][kc 0..63][row n 0..3071][tig 0..3] -> uint4 {hi(k0,k1), hi(k8,k9), lo(k0,k1), lo(k8,k9)}
// 8 * 64 * 3072 * 4 uint4 = 100.7 MB
__device__ uint4 g_wpack[8ull * 64 * 3072 * 4];

// ---------- helpers ----------
__device__ __forceinline__ void split_pair(float x, float y, uint32_t& hi, uint32_t& lo) {
    __nv_bfloat16 hx = __float2bfloat16(x);
    __nv_bfloat16 hy = __float2bfloat16(y);
    float rx = x - __bfloat162float(hx);
    float ry = y - __bfloat162float(hy);
    __nv_bfloat162 H2; H2.x = hx; H2.y = hy;
    __nv_bfloat162 L2 = __floats2bfloat162_rn(rx, ry);
    hi = *reinterpret_cast<uint32_t*>(&H2);
    lo = *reinterpret_cast<uint32_t*>(&L2);
}

__device__ __forceinline__ void mma_bf16(float* c, const uint32_t* a, uint32_t b0, uint32_t b1) {
    asm volatile(
        "mma.sync.aligned.m16n8k16.row.col.f32.bf16.bf16.f32 "
        "{%0,%1,%2,%3},{%4,%5,%6,%7},{%8,%9},{%0,%1,%2,%3};"
        : "+f"(c[0]), "+f"(c[1]), "+f"(c[2]), "+f"(c[3])
        : "r"(a[0]), "r"(a[1]), "r"(a[2]), "r"(a[3]), "r"(b0), "r"(b1));
}

// ---------- weight packing ----------
__global__ void pack_weights_kernel(const float* __restrict__ w_ih,
                                    const float* __restrict__ w_hh) {
    int64_t idx = (int64_t)blockIdx.x * blockDim.x + threadIdx.x;
    const int64_t total = 8ll * 64 * 3072 * 4;
    if (idx >= total) return;
    int tig = (int)(idx & 3);
    int64_t t2 = idx >> 2;
    int n = (int)(t2 % 3072);
    int64_t t3 = t2 / 3072;
    int kc = (int)(t3 & 63);
    int m  = (int)(t3 >> 6);
    int l = m >> 1, s = m & 1;
    const float* src = (s ? w_hh : w_ih) + ((int64_t)l * 3072 + n) * 1024 + kc * 16 + 2 * tig;
    float f0 = src[0], f1 = src[1], f2 = src[8], f3 = src[9];
    uint4 q;
    split_pair(f0, f1, q.x, q.z);
    split_pair(f2, f3, q.y, q.w);
    g_wpack[idx] = q;
}

// ---------- h0 init ----------
__global__ void init_h0_kernel(const float* __restrict__ h0) {
    int idx = blockIdx.x * blockDim.x + threadIdx.x;   // < L*B*H = 262144
    int l = idx >> 16;
    int rest = idx & 0xFFFF;
    int slot = (l + 1) & 1;                            // read-slot of wave l
    (&g_ring[slot][l][0][0])[rest] = h0[idx];
}

// ---------- wave kernel ----------
// grid = 128 (l = bx>>5, cb = bx&31), block = 512 threads (16 warps)
// warp = mstrip(0..3) x ksplit(0..1) x jhalf(0..1)
//   mstrip: rows [16*mstrip, +16)
//   jhalf : jt in {2*jhalf, 2*jhalf+1} (16 of the CTA's 32 columns)
//   ksplit: K-half [512*ksplit, +512) of each GEMM's reduction dim
// ksplit=1 warps dump partial acc into smem; ksplit=0 warps reduce + gates.
__global__ void __launch_bounds__(512, 1)
wave_kernel(const float* __restrict__ x,
            const float* __restrict__ b_ih,
            const float* __restrict__ b_hh,
            int w) {
    int l  = blockIdx.x >> 5;
    int cb = blockIdx.x & 31;
    int t  = w - l;
    if (t < 0 || t >= TT) return;

    const int rs = (w + 1) & 1;   // read slot
    const int ws = w & 1;         // write slot

    const float* inp   = (l == 0) ? (x + (int64_t)t * BB * HID) : &g_ring[rs][l - 1][0][0];
    const float* hprev = &g_ring[rs][l][0][0];
    float*       hout  = &g_ring[ws][l][0][0];

    const int lane = threadIdx.x & 31;
    const int warp = threadIdx.x >> 5;
    const int mstrip = warp & 3;
    const int ksplit = (warp >> 2) & 1;
    const int jhalf  = warp >> 3;
    const int gid = lane >> 2;    // 0..7
    const int tig = lane & 3;     // 0..3
    const int c0 = cb * 32;

    // acc[group][jt_local][reg]; groups: 0=r(gi+gh), 1=z(gi+gh), 2=gi_n, 3=gh_n
    float acc[4][2][4];
#pragma unroll
    for (int g = 0; g < 4; ++g)
#pragma unroll
        for (int j = 0; j < 2; ++j)
#pragma unroll
            for (int r = 0; r < 4; ++r) acc[g][j][r] = 0.f;

    const int r0 = mstrip * 16 + gid;
    const int kc_lo = ksplit * 32;
    const int kc_hi = kc_lo + 32;

#pragma unroll
    for (int phase = 0; phase < 2; ++phase) {
        const float* act = phase ? hprev : inp;
        const uint4* wp = &g_wpack[(int64_t)(l * 2 + phase) * 64 * 3072 * 4];
        const int g_third = phase ? 3 : 2;   // phase0 accumulates gi_n, phase1 gh_n

#pragma unroll 2
        for (int kc = kc_lo; kc < kc_hi; ++kc) {
            // ---- A fragments (activations, split on the fly) ----
            uint32_t Ah[4], Al[4];
            const float* ar0 = act + (int64_t)r0 * HID + kc * 16 + 2 * tig;
            const float* ar1 = ar0 + 8 * HID;
            float2 p;
            p = *(const float2*)(ar0);     split_pair(p.x, p.y, Ah[0], Al[0]);
            p = *(const float2*)(ar1);     split_pair(p.x, p.y, Ah[1], Al[1]);
            p = *(const float2*)(ar0 + 8); split_pair(p.x, p.y, Ah[2], Al[2]);
            p = *(const float2*)(ar1 + 8); split_pair(p.x, p.y, Ah[3], Al[3]);

            const uint4* wkc = wp + (int64_t)kc * 3072 * 4;

            // ---- B fragments + 3-term split MMAs ----
#pragma unroll
            for (int gg = 0; gg < 3; ++gg) {
                const int g = (gg < 2) ? gg : g_third;
                const int goff = gg * HID;  // weight row block: r@0, z@H, n@2H
#pragma unroll
                for (int jtl = 0; jtl < 2; ++jtl) {
                    const int jt = jhalf * 2 + jtl;
                    const int n = goff + c0 + jt * 8 + gid;
                    uint4 q = wkc[n * 4 + tig];
                    float* C = acc[g][jtl];
                    mma_bf16(C, Ah, q.x, q.y);   // Ah * Wh
                    mma_bf16(C, Ah, q.z, q.w);   // Ah * Wl
                    mma_bf16(C, Al, q.x, q.y);   // Al * Wh
                }
            }
        }
    }

    // ---- cross-warp K reduction through smem ----
    // ksplit=1 warps: warp ids 4..7 and 12..15 -> slot = jhalf*4 + mstrip (0..7)
    __shared__ float red[8][32][32];
    if (ksplit == 1) {
        const float* af = &acc[0][0][0];
        float* dst = &red[jhalf * 4 + mstrip][lane][0];
#pragma unroll
        for (int i = 0; i < 32; ++i) dst[i] = af[i];
    }
    __syncthreads();
    if (ksplit == 1) return;
    {
        float* af = &acc[0][0][0];
        const float* src = &red[jhalf * 4 + mstrip][lane][0];
#pragma unroll
        for (int i = 0; i < 32; ++i) af[i] += src[i];
    }

    // ---- gates (thread-local: all 4 gate pre-acts for (b,c) live in same regs) ----
    const float* bi = b_ih + l * 3 * HID;
    const float* bh = b_hh + l * 3 * HID;
#pragma unroll
    for (int jtl = 0; jtl < 2; ++jtl) {
        const int jbase = (jhalf * 2 + jtl) * 8 + tig * 2;
#pragma unroll
        for (int half = 0; half < 2; ++half) {
            const int b = mstrip * 16 + gid + half * 8;
#pragma unroll
            for (int par = 0; par < 2; ++par) {
                const int c = c0 + jbase + par;
                const int ri = half * 2 + par;
                float pr  = acc[0][jtl][ri] + bi[c]           + bh[c];
                float pz  = acc[1][jtl][ri] + bi[HID + c]     + bh[HID + c];
                float gin = acc[2][jtl][ri] + bi[2 * HID + c];
                float ghn = acc[3][jtl][ri] + bh[2 * HID + c];
                float rr = 1.f / (1.f + __expf(-pr));
                float zz = 1.f / (1.f + __expf(-pz));
                float nn = tanhf(gin + rr * ghn);
                float hp = hprev[(int64_t)b * HID + c];
                hout[(int64_t)b * HID + c] = (1.f - zz) * nn + zz * hp;
            }
        }
    }
}

// ---------- output copy ----------
__global__ void copy_out_kernel(float* __restrict__ out) {
    int idx = blockIdx.x * blockDim.x + threadIdx.x;   // < L*B*H
    int l = idx >> 16;
    int rest = idx & 0xFFFF;
    int slot = (TT - 1 + l) & 1;  // slot of the final write of layer l (wave T-1+l)
    out[idx] = (&g_ring[slot][l][0][0])[rest];
}

// ---------- launch ----------
extern "C" void kernel_launch(void* const* d_in, const int* in_sizes, int n_in,
                              void* d_out, int out_size) {
    const float* x    = (const float*)d_in[0];
    const float* h0   = (const float*)d_in[1];
    const float* w_ih = (const float*)d_in[2];
    const float* w_hh = (const float*)d_in[3];
    const float* b_ih = (const float*)d_in[4];
    const float* b_hh = (const float*)d_in[5];
    float* out = (float*)d_out;

    // 1) pack weights into split-bf16 fragment-major layout
    {
        int64_t total = 8ll * 64 * 3072 * 4;
        int thr = 256;
        int blks = (int)((total + thr - 1) / thr);
        pack_weights_kernel<<<blks, thr>>>(w_ih, w_hh);
    }
    // 2) place h0 into each layer's first read slot
    init_h0_kernel<<<(LAY * BB * HID) / 256, 256>>>(h0);

    // 3) wavefront: 515 dependent waves, stream-ordered
    for (int w = 0; w < NWAVE; ++w) {
        wave_kernel<<<128, 512>>>(x, b_ih, b_hh, w);
    }

    // 4) gather final hidden states
    copy_out_kernel<<<(LAY * BB * HID) / 256, 256>>>(out);
}